// round 1
// baseline (speedup 1.0000x reference)
#include <cuda_runtime.h>
#include <math.h>

#define B 64
#define C 512
#define HW 1024
#define R 32
#define TILE_N 256
#define T1 128
#define TILES 4        // HW / TILE_N
#define NSLOT 16       // TILES * (T1/32) pooled-partial slots per (b,c)

// ---------------- scratch (device globals: no allocation allowed) -------------
__device__ float g_feat[B * R * HW];        // 8 MB   feat_raw = w_eig @ x (no bias)
__device__ float g_poolpart[B * NSLOT * C]; // 2 MB   partial sums for pooled
__device__ float g_sp[B * HW];              // 256 KB spatial logits (no bias)
__device__ float g_ca[B * C];               // 128 KB channel attention (sigmoid)
__device__ float g_att[B * HW];             // 256 KB eigen_att * spatial_att

// ============================================================================
// Pass 1: one sweep over x. Per CTA: (batch b, tile of 256 n), 128 threads,
// 2 n per thread. Computes feat (32 accumulators x 2n in regs), spatial
// logits, and pooled partial sums (warp shfl reduce per c).
// w_eig staged in smem in two 256-channel halves (32 KB, static-smem safe).
// ============================================================================
__global__ __launch_bounds__(T1) void pass1(const float* __restrict__ x,
                                            const float* __restrict__ w_eig,
                                            const float* __restrict__ w_sp) {
    __shared__ float we_s[256 * R];   // [cc][r], broadcast-friendly
    __shared__ float wsp_s[256];

    int b = blockIdx.x / TILES;
    int tile = blockIdx.x % TILES;
    int n0 = tile * TILE_N;
    int tid = threadIdx.x, lane = tid & 31, warp = tid >> 5;

    float acc0[R], acc1[R];
#pragma unroll
    for (int r = 0; r < R; r++) { acc0[r] = 0.f; acc1[r] = 0.f; }
    float sp0 = 0.f, sp1 = 0.f;

    const float* xb = x + (size_t)b * C * HW + n0 + 2 * tid;
    float* pp = g_poolpart + ((size_t)b * NSLOT + tile * 4 + warp) * C;

    for (int half = 0; half < 2; half++) {
        int cbase = half * 256;
        __syncthreads();
        for (int idx = tid; idx < 256 * R; idx += T1) {
            int rr = idx >> 8;      // 0..31
            int cc = idx & 255;     // coalesced gmem read
            we_s[cc * R + rr] = w_eig[rr * C + cbase + cc];
        }
        for (int idx = tid; idx < 256; idx += T1) wsp_s[idx] = w_sp[cbase + idx];
        __syncthreads();

#pragma unroll 2
        for (int cc = 0; cc < 256; cc++) {
            float2 xv = *(const float2*)(xb + (size_t)(cbase + cc) * HW);
            float ws = wsp_s[cc];
            sp0 = fmaf(ws, xv.x, sp0);
            sp1 = fmaf(ws, xv.y, sp1);
#pragma unroll
            for (int r = 0; r < R; r++) {
                float w = we_s[cc * R + r];
                acc0[r] = fmaf(w, xv.x, acc0[r]);
                acc1[r] = fmaf(w, xv.y, acc1[r]);
            }
            // pooled partial: sum this warp's 64 n values for channel c
            float ps = xv.x + xv.y;
            ps += __shfl_xor_sync(0xffffffffu, ps, 16);
            ps += __shfl_xor_sync(0xffffffffu, ps, 8);
            ps += __shfl_xor_sync(0xffffffffu, ps, 4);
            ps += __shfl_xor_sync(0xffffffffu, ps, 2);
            ps += __shfl_xor_sync(0xffffffffu, ps, 1);
            if (lane == 0) pp[cbase + cc] = ps;
        }
    }

#pragma unroll
    for (int r = 0; r < R; r++) {
        float2 v; v.x = acc0[r]; v.y = acc1[r];
        *(float2*)(g_feat + ((size_t)(b * R + r)) * HW + n0 + 2 * tid) = v;
    }
    *(float2*)(g_sp + (size_t)b * HW + n0 + 2 * tid) = make_float2(sp0, sp1);
}

// ============================================================================
// Pass 2: one CTA (256 threads) per batch. pooled -> channel MLP, mu from
// pooled (b_eig cancels in feat_c), cov via warp outer-products, 5-step
// power iteration, att projection + min/max + sigmoids -> g_att, g_ca.
// ============================================================================
__global__ __launch_bounds__(256) void pass2(const float* __restrict__ w_fc1,
                                             const float* __restrict__ b_fc1,
                                             const float* __restrict__ w_fc2,
                                             const float* __restrict__ b_fc2,
                                             const float* __restrict__ w_eig,
                                             const float* __restrict__ b_sp,
                                             const float* __restrict__ v0) {
    __shared__ float s_pool[C];
    __shared__ float s_mu[R];
    __shared__ float s_ca1[R];
    __shared__ float s_cov[R * R];
    __shared__ float s_v[R];
    __shared__ float s_buf[8 * R * R];   // 32 KB: fcT chunk (front), then per-warp cov partials
    __shared__ float s_redmin[8], s_redmax[8];
    __shared__ float s_c0, s_amin, s_amax;

    int b = blockIdx.x;
    int tid = threadIdx.x, lane = tid & 31, warp = tid >> 5;

    // 1. pooled = sum of 16 partials / HW
    for (int c = tid; c < C; c += 256) {
        float s = 0.f;
#pragma unroll
        for (int k = 0; k < NSLOT; k++) s += g_poolpart[((size_t)b * NSLOT + k) * C + c];
        s_pool[c] = s * (1.0f / HW);
    }
    __syncthreads();

    // 2. ca1 = relu(pooled @ w_fc1^T + b_fc1); mu = w_eig @ pooled
    for (int k = 0; k < 4; k++) {
        int r = warp + k * 8;
        float s1 = 0.f, s2 = 0.f;
        for (int c = lane; c < C; c += 32) {
            float p = s_pool[c];
            s1 = fmaf(p, w_fc1[r * C + c], s1);
            s2 = fmaf(p, w_eig[r * C + c], s2);
        }
        for (int o = 16; o > 0; o >>= 1) {
            s1 += __shfl_xor_sync(0xffffffffu, s1, o);
            s2 += __shfl_xor_sync(0xffffffffu, s2, o);
        }
        if (lane == 0) {
            s_ca1[r] = fmaxf(s1 + b_fc1[r], 0.f);
            s_mu[r] = s2;
        }
    }
    __syncthreads();

    // 3. channel attention: sigmoid(ca1 @ w_fc2^T + b_fc2)
    for (int c = tid; c < C; c += 256) {
        float a = b_fc2[c];
#pragma unroll
        for (int r = 0; r < R; r++) a = fmaf(s_ca1[r], w_fc2[c * R + r], a);
        g_ca[(size_t)b * C + c] = 1.f / (1.f + expf(-a));
    }

    // 4. cov: per-warp outer products over n-chunks of 64
    float covrow[R];
#pragma unroll
    for (int s = 0; s < R; s++) covrow[s] = 0.f;
    const int CH = 64;
    float* fcT = s_buf;  // [CH][33], conflict-free transposed layout
    for (int ch = 0; ch < HW / CH; ch++) {
        __syncthreads();
        for (int it = 0; it < (R * CH) / 256; it++) {  // 8 iterations
            int idx = tid + it * 256;
            int r = idx >> 6, n = idx & 63;
            fcT[n * 33 + r] = g_feat[((size_t)(b * R + r)) * HW + ch * CH + n] - s_mu[r];
        }
        __syncthreads();
        for (int j = 0; j < CH / 8; j++) {
            int n = warp * 8 + j;
            float a = fcT[n * 33 + lane];
#pragma unroll
            for (int s = 0; s < R; s++)
                covrow[s] = fmaf(a, __shfl_sync(0xffffffffu, a, s), covrow[s]);
        }
    }
    __syncthreads();
    // store per-warp partials (transposed store = conflict-free)
#pragma unroll
    for (int s = 0; s < R; s++) s_buf[(warp * R + s) * R + lane] = covrow[s];
    __syncthreads();

    // 5. reduce 8 warp partials; /(HW-1) + 1e-5 I
    for (int e = tid; e < R * R; e += 256) {
        float s = 0.f;
#pragma unroll
        for (int w = 0; w < 8; w++) s += s_buf[w * R * R + e];
        s *= (1.0f / (HW - 1));
        if ((e >> 5) == (e & 31)) s += 1e-5f;
        s_cov[e] = s;   // symmetric, so [s][r] == [r][s]
    }
    __syncthreads();

    // 6. power iteration (warp 0)
    if (warp == 0) {
        float v = v0[b * R + lane];
        float nr = v * v;
        for (int o = 16; o > 0; o >>= 1) nr += __shfl_xor_sync(0xffffffffu, nr, o);
        v = v / sqrtf(nr);
        for (int it = 0; it < 5; it++) {
            float nv = 0.f;
#pragma unroll
            for (int s = 0; s < R; s++)
                nv = fmaf(s_cov[s * R + lane], __shfl_sync(0xffffffffu, v, s), nv);
            float nn = nv * nv;
            for (int o = 16; o > 0; o >>= 1) nn += __shfl_xor_sync(0xffffffffu, nn, o);
            v = nv / (sqrtf(nn) + 1e-10f);
        }
        s_v[lane] = v;
        float c0 = v * s_mu[lane];  // v . mu  (constant offset of att)
        for (int o = 16; o > 0; o >>= 1) c0 += __shfl_xor_sync(0xffffffffu, c0, o);
        if (lane == 0) s_c0 = c0;
    }
    __syncthreads();

    // 7. att[n] = v . feat_c[:,n] = v . feat_raw[:,n] - c0 ; min/max; sigmoids
    float attv[4];
#pragma unroll
    for (int k = 0; k < 4; k++) {
        int n = k * 256 + tid;
        float a = 0.f;
#pragma unroll
        for (int r = 0; r < R; r++)
            a = fmaf(s_v[r], g_feat[((size_t)(b * R + r)) * HW + n], a);
        attv[k] = a - s_c0;
    }
    float mn = attv[0], mx = attv[0];
#pragma unroll
    for (int k = 1; k < 4; k++) { mn = fminf(mn, attv[k]); mx = fmaxf(mx, attv[k]); }
    for (int o = 16; o > 0; o >>= 1) {
        mn = fminf(mn, __shfl_xor_sync(0xffffffffu, mn, o));
        mx = fmaxf(mx, __shfl_xor_sync(0xffffffffu, mx, o));
    }
    if (lane == 0) { s_redmin[warp] = mn; s_redmax[warp] = mx; }
    __syncthreads();
    if (tid == 0) {
        float a = s_redmin[0], m = s_redmax[0];
        for (int w = 1; w < 8; w++) { a = fminf(a, s_redmin[w]); m = fmaxf(m, s_redmax[w]); }
        s_amin = a; s_amax = m;
    }
    __syncthreads();
    float amin = s_amin;
    float denom = (s_amax - amin) + 1e-10f;
    float bspv = b_sp[0];
#pragma unroll
    for (int k = 0; k < 4; k++) {
        int n = k * 256 + tid;
        float e = 1.f / (1.f + expf(-((attv[k] - amin) / denom)));
        float sl = g_sp[(size_t)b * HW + n] + bspv;
        float sa = 1.f / (1.f + expf(-sl));
        g_att[(size_t)b * HW + n] = e * sa;
    }
}

// ============================================================================
// Pass 3: out = x * (1 + ca[b,c] * att[b,n])  (float4 vectorized, 1 f4/thread)
// ============================================================================
__global__ __launch_bounds__(256) void pass3(const float* __restrict__ x,
                                             float* __restrict__ out) {
    unsigned int i = blockIdx.x * 256u + threadIdx.x;  // float4 index, < 2^23
    int n4 = i & 255;             // HW/4 = 256
    int c = (i >> 8) & (C - 1);
    int b = i >> 17;              // 8 + 9
    float ca = g_ca[b * C + c];
    float4 at = ((const float4*)g_att)[(size_t)b * (HW / 4) + n4];
    float4 xv = ((const float4*)x)[i];
    float4 o;
    o.x = fmaf(xv.x, ca * at.x, xv.x);
    o.y = fmaf(xv.y, ca * at.y, xv.y);
    o.z = fmaf(xv.z, ca * at.z, xv.z);
    o.w = fmaf(xv.w, ca * at.w, xv.w);
    ((float4*)out)[i] = o;
}

extern "C" void kernel_launch(void* const* d_in, const int* in_sizes, int n_in,
                              void* d_out, int out_size) {
    const float* x     = (const float*)d_in[0];
    const float* w_fc1 = (const float*)d_in[1];
    const float* b_fc1 = (const float*)d_in[2];
    const float* w_fc2 = (const float*)d_in[3];
    const float* b_fc2 = (const float*)d_in[4];
    const float* w_eig = (const float*)d_in[5];
    /* d_in[6] = b_eig: cancels in feat_c and in mu -> unused */
    const float* w_sp  = (const float*)d_in[7];
    const float* b_sp  = (const float*)d_in[8];
    const float* v0    = (const float*)d_in[9];
    float* out = (float*)d_out;

    pass1<<<B * TILES, T1>>>(x, w_eig, w_sp);
    pass2<<<B, 256>>>(w_fc1, b_fc1, w_fc2, b_fc2, w_eig, b_sp, v0);
    pass3<<<(B * C * HW / 4) / 256, 256>>>(x, out);
}

// round 2
// speedup vs baseline: 1.0710x; 1.0710x over previous
#include <cuda_runtime.h>
#include <math.h>

#define B 64
#define C 512
#define HW 1024
#define R 32
#define T1 128
#define TILE_N 128
#define NTILE 8        // HW / TILE_N
#define NSLOT 32       // NTILE * 4 warps pooled-partial slots per (b,c)

// ---------------- scratch (device globals: no allocation allowed) -------------
__device__ float g_feat[B * R * HW];        // 8 MB   feat_raw = w_eig @ x (no bias)
__device__ float g_poolpart[B * NSLOT * C]; // 4 MB   partial sums for pooled
__device__ float g_sp[B * HW];              // 256 KB spatial logits (no bias)
__device__ float g_ca[B * C];               // 128 KB channel attention (sigmoid)
__device__ float g_att[B * HW];             // 256 KB eigen_att * spatial_att

// ============================================================================
// Pass 1: one sweep over x. CTA = (batch b, tile of 128 n), 128 threads,
// 1 n per thread -> grid 512 (single wave at 4 CTAs/SM).
// feat accumulators (32) in regs; w_eig staged in smem as [cc][36] so the
// inner loop is 8x LDS.128 + 32 FFMA per channel (FFMA-issue-limited).
// ============================================================================
__global__ __launch_bounds__(T1, 4) void pass1(const float* __restrict__ x,
                                               const float* __restrict__ w_eig,
                                               const float* __restrict__ w_sp) {
    __shared__ float we_s[256][36];   // padded: 16B-aligned rows, 4-way STS conflicts only
    __shared__ float wsp_s[256];

    int b = blockIdx.x / NTILE;
    int tile = blockIdx.x % NTILE;
    int n0 = tile * TILE_N;
    int tid = threadIdx.x, lane = tid & 31, warp = tid >> 5;

    float acc[R];
#pragma unroll
    for (int r = 0; r < R; r++) acc[r] = 0.f;
    float sp = 0.f;

    const float* xb = x + (size_t)b * C * HW + n0 + tid;
    float* pp = g_poolpart + ((size_t)b * NSLOT + tile * 4 + warp) * C;

    for (int half = 0; half < 2; half++) {
        int cbase = half * 256;
        __syncthreads();
        for (int idx = tid; idx < 256 * R; idx += T1) {
            int rr = idx >> 8;      // 0..31
            int cc = idx & 255;     // coalesced gmem read
            we_s[cc][rr] = w_eig[rr * C + cbase + cc];
        }
        for (int idx = tid; idx < 256; idx += T1) wsp_s[idx] = w_sp[cbase + idx];
        __syncthreads();

#pragma unroll 2
        for (int cc = 0; cc < 256; cc++) {
            float xv = __ldg(xb + (size_t)(cbase + cc) * HW);
            sp = fmaf(wsp_s[cc], xv, sp);
            const float4* wrow = (const float4*)&we_s[cc][0];
#pragma unroll
            for (int q = 0; q < 8; q++) {
                float4 w4 = wrow[q];
                acc[4 * q + 0] = fmaf(w4.x, xv, acc[4 * q + 0]);
                acc[4 * q + 1] = fmaf(w4.y, xv, acc[4 * q + 1]);
                acc[4 * q + 2] = fmaf(w4.z, xv, acc[4 * q + 2]);
                acc[4 * q + 3] = fmaf(w4.w, xv, acc[4 * q + 3]);
            }
            // pooled partial: sum this warp's 32 n values for channel c
            float ps = xv;
            ps += __shfl_xor_sync(0xffffffffu, ps, 16);
            ps += __shfl_xor_sync(0xffffffffu, ps, 8);
            ps += __shfl_xor_sync(0xffffffffu, ps, 4);
            ps += __shfl_xor_sync(0xffffffffu, ps, 2);
            ps += __shfl_xor_sync(0xffffffffu, ps, 1);
            if (lane == 0) pp[cbase + cc] = ps;
        }
    }

#pragma unroll
    for (int r = 0; r < R; r++)
        g_feat[((size_t)(b * R + r)) * HW + n0 + tid] = acc[r];
    g_sp[(size_t)b * HW + n0 + tid] = sp;
}

// ============================================================================
// Pass 2: one CTA (256 threads) per batch. pooled -> channel MLP, mu from
// pooled (b_eig cancels in feat_c), cov via shfl-free per-thread 4-element
// ownership (1 LDS + 1 LDS.128 + 4 FFMA per n), 5-step power iteration,
// att projection + min/max + sigmoids -> g_att, g_ca.
// ============================================================================
__global__ __launch_bounds__(256) void pass2(const float* __restrict__ w_fc1,
                                             const float* __restrict__ b_fc1,
                                             const float* __restrict__ w_fc2,
                                             const float* __restrict__ b_fc2,
                                             const float* __restrict__ w_eig,
                                             const float* __restrict__ b_sp,
                                             const float* __restrict__ v0) {
    __shared__ float s_pool[C];
    __shared__ float s_mu[R];
    __shared__ float s_ca1[R];
    __shared__ float s_cov[R * R];
    __shared__ float s_v[R];
    __shared__ float fcT[256][36];    // 36 KB, 16B-aligned rows
    __shared__ float s_redmin[8], s_redmax[8];
    __shared__ float s_c0, s_amin, s_amax;

    int b = blockIdx.x;
    int tid = threadIdx.x, lane = tid & 31, warp = tid >> 5;

    // 1. pooled = sum of 32 partials / HW
    for (int c = tid; c < C; c += 256) {
        float s = 0.f;
#pragma unroll
        for (int k = 0; k < NSLOT; k++) s += g_poolpart[((size_t)b * NSLOT + k) * C + c];
        s_pool[c] = s * (1.0f / HW);
    }
    __syncthreads();

    // 2. ca1 = relu(pooled @ w_fc1^T + b_fc1); mu = w_eig @ pooled
    for (int k = 0; k < 4; k++) {
        int r = warp + k * 8;
        float s1 = 0.f, s2 = 0.f;
        for (int c = lane; c < C; c += 32) {
            float p = s_pool[c];
            s1 = fmaf(p, w_fc1[r * C + c], s1);
            s2 = fmaf(p, w_eig[r * C + c], s2);
        }
        for (int o = 16; o > 0; o >>= 1) {
            s1 += __shfl_xor_sync(0xffffffffu, s1, o);
            s2 += __shfl_xor_sync(0xffffffffu, s2, o);
        }
        if (lane == 0) {
            s_ca1[r] = fmaxf(s1 + b_fc1[r], 0.f);
            s_mu[r] = s2;
        }
    }
    __syncthreads();

    // 3. channel attention: sigmoid(ca1 @ w_fc2^T + b_fc2)
    for (int c = tid; c < C; c += 256) {
        float a = b_fc2[c];
#pragma unroll
        for (int r = 0; r < R; r++) a = fmaf(s_ca1[r], w_fc2[c * R + r], a);
        g_ca[(size_t)b * C + c] = 1.f / (1.f + expf(-a));
    }

    // 4. cov: each thread owns 4 elements cov[r][s0..s0+3]
    int my_r = tid >> 3;            // 0..31
    int s0 = (tid & 7) * 4;         // 0,4,...,28
    float covacc[4] = {0.f, 0.f, 0.f, 0.f};
    for (int ch = 0; ch < HW / 256; ch++) {
        __syncthreads();
        for (int it = 0; it < (R * 256) / 256; it++) {   // 32 iterations
            int idx = tid + it * 256;
            int r = idx >> 8, n = idx & 255;
            fcT[n][r] = g_feat[((size_t)(b * R + r)) * HW + ch * 256 + n] - s_mu[r];
        }
        __syncthreads();
#pragma unroll 4
        for (int n = 0; n < 256; n++) {
            float fr = fcT[n][my_r];
            float4 fs = *(const float4*)&fcT[n][s0];
            covacc[0] = fmaf(fr, fs.x, covacc[0]);
            covacc[1] = fmaf(fr, fs.y, covacc[1]);
            covacc[2] = fmaf(fr, fs.z, covacc[2]);
            covacc[3] = fmaf(fr, fs.w, covacc[3]);
        }
    }
#pragma unroll
    for (int i = 0; i < 4; i++) {
        float v = covacc[i] * (1.0f / (HW - 1));
        if (my_r == s0 + i) v += 1e-5f;
        s_cov[my_r * R + s0 + i] = v;
    }
    __syncthreads();

    // 5. power iteration (warp 0)
    if (warp == 0) {
        float v = v0[b * R + lane];
        float nr = v * v;
        for (int o = 16; o > 0; o >>= 1) nr += __shfl_xor_sync(0xffffffffu, nr, o);
        v = v / sqrtf(nr);
        for (int it = 0; it < 5; it++) {
            float nv = 0.f;
#pragma unroll
            for (int s = 0; s < R; s++)
                nv = fmaf(s_cov[s * R + lane], __shfl_sync(0xffffffffu, v, s), nv);
            float nn = nv * nv;
            for (int o = 16; o > 0; o >>= 1) nn += __shfl_xor_sync(0xffffffffu, nn, o);
            v = nv / (sqrtf(nn) + 1e-10f);
        }
        s_v[lane] = v;
        float c0 = v * s_mu[lane];  // v . mu  (constant offset of att)
        for (int o = 16; o > 0; o >>= 1) c0 += __shfl_xor_sync(0xffffffffu, c0, o);
        if (lane == 0) s_c0 = c0;
    }
    __syncthreads();

    // 6. att[n] = v . feat_raw[:,n] - c0 ; min/max; sigmoids
    float attv[4];
#pragma unroll
    for (int k = 0; k < 4; k++) {
        int n = k * 256 + tid;
        float a = 0.f;
#pragma unroll
        for (int r = 0; r < R; r++)
            a = fmaf(s_v[r], g_feat[((size_t)(b * R + r)) * HW + n], a);
        attv[k] = a - s_c0;
    }
    float mn = attv[0], mx = attv[0];
#pragma unroll
    for (int k = 1; k < 4; k++) { mn = fminf(mn, attv[k]); mx = fmaxf(mx, attv[k]); }
    for (int o = 16; o > 0; o >>= 1) {
        mn = fminf(mn, __shfl_xor_sync(0xffffffffu, mn, o));
        mx = fmaxf(mx, __shfl_xor_sync(0xffffffffu, mx, o));
    }
    if (lane == 0) { s_redmin[warp] = mn; s_redmax[warp] = mx; }
    __syncthreads();
    if (tid == 0) {
        float a = s_redmin[0], m = s_redmax[0];
        for (int w = 1; w < 8; w++) { a = fminf(a, s_redmin[w]); m = fmaxf(m, s_redmax[w]); }
        s_amin = a; s_amax = m;
    }
    __syncthreads();
    float amin = s_amin;
    float denom = (s_amax - amin) + 1e-10f;
    float bspv = b_sp[0];
#pragma unroll
    for (int k = 0; k < 4; k++) {
        int n = k * 256 + tid;
        float e = 1.f / (1.f + expf(-((attv[k] - amin) / denom)));
        float sl = g_sp[(size_t)b * HW + n] + bspv;
        float sa = 1.f / (1.f + expf(-sl));
        g_att[(size_t)b * HW + n] = e * sa;
    }
}

// ============================================================================
// Pass 3: out = x * (1 + ca[b,c] * att[b,n])  (float4 vectorized)
// ============================================================================
__global__ __launch_bounds__(256) void pass3(const float* __restrict__ x,
                                             float* __restrict__ out) {
    unsigned int i = blockIdx.x * 256u + threadIdx.x;  // float4 index
    int n4 = i & 255;             // HW/4 = 256
    int c = (i >> 8) & (C - 1);
    int b = i >> 17;
    float ca = g_ca[b * C + c];
    float4 at = ((const float4*)g_att)[(size_t)b * (HW / 4) + n4];
    float4 xv = ((const float4*)x)[i];
    float4 o;
    o.x = fmaf(xv.x, ca * at.x, xv.x);
    o.y = fmaf(xv.y, ca * at.y, xv.y);
    o.z = fmaf(xv.z, ca * at.z, xv.z);
    o.w = fmaf(xv.w, ca * at.w, xv.w);
    ((float4*)out)[i] = o;
}

extern "C" void kernel_launch(void* const* d_in, const int* in_sizes, int n_in,
                              void* d_out, int out_size) {
    const float* x     = (const float*)d_in[0];
    const float* w_fc1 = (const float*)d_in[1];
    const float* b_fc1 = (const float*)d_in[2];
    const float* w_fc2 = (const float*)d_in[3];
    const float* b_fc2 = (const float*)d_in[4];
    const float* w_eig = (const float*)d_in[5];
    /* d_in[6] = b_eig: cancels in feat_c and in mu -> unused */
    const float* w_sp  = (const float*)d_in[7];
    const float* b_sp  = (const float*)d_in[8];
    const float* v0    = (const float*)d_in[9];
    float* out = (float*)d_out;

    pass1<<<B * NTILE, T1>>>(x, w_eig, w_sp);
    pass2<<<B, 256>>>(w_fc1, b_fc1, w_fc2, b_fc2, w_eig, b_sp, v0);
    pass3<<<(B * C * HW / 4) / 256, 256>>>(x, out);
}

// round 3
// speedup vs baseline: 1.8685x; 1.7446x over previous
#include <cuda_runtime.h>
#include <math.h>

#define B 64
#define C 512
#define HW 1024
#define R 32
#define T1 128
#define TILE_N 128
#define NTILE 8        // HW / TILE_N
#define NSLOT 8        // one pooled partial per tile

// ---------------- scratch (device globals: no allocation allowed) -------------
__device__ float g_feat[B * R * HW];        // 8 MB   feat_raw = w_eig @ x (no bias)
__device__ float g_poolpart[B * NSLOT * C]; // 1 MB   partial sums for pooled
__device__ float g_covpart[B * 4 * R * R];  // 1 MB   raw Gram partials (4 n-quarters)
__device__ float g_sp[B * HW];              // 256 KB spatial logits (no bias)
__device__ float g_ca[B * C];               // 128 KB channel attention (sigmoid)
__device__ float g_att[B * HW];             // 256 KB eigen_att * spatial_att

// ============================================================================
// Pass 1: register-tiled GEMM. CTA = (b, 128-n tile), 128 threads.
// Thread computes 8r x 4n: per channel 3x LDS.128 + 32 FFMA.
// x double-buffered through smem in chunks of 8 channels (MLP=8 prefetch).
// w_eig staged in smem in two 256-channel halves. Side products (pooled,
// spatial logits) on designated warps, rotated by tile to balance SMSPs.
// ============================================================================
__global__ __launch_bounds__(T1, 4) void pass1(const float* __restrict__ x,
                                               const float* __restrict__ w_eig,
                                               const float* __restrict__ w_sp) {
    __shared__ __align__(16) float we_s[256][36];   // 36 KB (rows 144B, 16B-aligned)
    __shared__ __align__(16) float xs[2][8][128];   // 8 KB double buffer
    __shared__ float wsp_s[256];
    __shared__ float spool[512];

    int b = blockIdx.x >> 3;
    int tile = blockIdx.x & 7;
    int n0 = tile << 7;
    int tid = threadIdx.x, lane = tid & 31, warp = tid >> 5;
    int r0 = warp << 3;          // 8 r rows per warp
    int ncol = lane << 2;        // 4 n cols per thread
    int spw = tile & 3;          // spatial-logit duty warp
    int plw = (tile + 1) & 3;    // pooled duty warp

    // stage w_eig half 0 (channels 0..255), transposed to [cc][r]
    for (int idx = tid; idx < 256 * 32; idx += T1) {
        int rr = idx >> 8;
        int cc = idx & 255;
        we_s[cc][rr] = w_eig[rr * C + cc];
    }
    for (int idx = tid; idx < 256; idx += T1) wsp_s[idx] = w_sp[idx];

    const float* xb = x + ((size_t)b * C) * HW + n0;

    // prefetch chunk 0 (channels 0..7)
    float pf[8];
#pragma unroll
    for (int k = 0; k < 8; k++) pf[k] = xb[(size_t)k * HW + tid];
#pragma unroll
    for (int k = 0; k < 8; k++) xs[0][k][tid] = pf[k];

    float acc[32];
#pragma unroll
    for (int i = 0; i < 32; i++) acc[i] = 0.f;
    float sp4[4] = {0.f, 0.f, 0.f, 0.f};

    __syncthreads();

    int buf = 0;
    for (int chunk = 0; chunk < 64; chunk++) {
        if (chunk == 32) {
            // chunk-31-end sync guarantees all half-0 reads of we_s are done
            for (int idx = tid; idx < 256 * 32; idx += T1) {
                int rr = idx >> 8;
                int cc = idx & 255;
                we_s[cc][rr] = w_eig[rr * C + 256 + cc];
            }
            for (int idx = tid; idx < 256; idx += T1) wsp_s[idx] = w_sp[256 + idx];
            __syncthreads();
        }
        int cbase = chunk << 3;
        bool more = chunk < 63;
        if (more) {
#pragma unroll
            for (int k = 0; k < 8; k++)
                pf[k] = xb[(size_t)(cbase + 8 + k) * HW + tid];
        }
#pragma unroll
        for (int k = 0; k < 8; k++) {
            int cl = (cbase + k) & 255;
            float4 xv = *(const float4*)&xs[buf][k][ncol];
            float4 w0 = *(const float4*)&we_s[cl][r0];
            float4 w1 = *(const float4*)&we_s[cl][r0 + 4];
            acc[0]  = fmaf(w0.x, xv.x, acc[0]);
            acc[1]  = fmaf(w0.x, xv.y, acc[1]);
            acc[2]  = fmaf(w0.x, xv.z, acc[2]);
            acc[3]  = fmaf(w0.x, xv.w, acc[3]);
            acc[4]  = fmaf(w0.y, xv.x, acc[4]);
            acc[5]  = fmaf(w0.y, xv.y, acc[5]);
            acc[6]  = fmaf(w0.y, xv.z, acc[6]);
            acc[7]  = fmaf(w0.y, xv.w, acc[7]);
            acc[8]  = fmaf(w0.z, xv.x, acc[8]);
            acc[9]  = fmaf(w0.z, xv.y, acc[9]);
            acc[10] = fmaf(w0.z, xv.z, acc[10]);
            acc[11] = fmaf(w0.z, xv.w, acc[11]);
            acc[12] = fmaf(w0.w, xv.x, acc[12]);
            acc[13] = fmaf(w0.w, xv.y, acc[13]);
            acc[14] = fmaf(w0.w, xv.z, acc[14]);
            acc[15] = fmaf(w0.w, xv.w, acc[15]);
            acc[16] = fmaf(w1.x, xv.x, acc[16]);
            acc[17] = fmaf(w1.x, xv.y, acc[17]);
            acc[18] = fmaf(w1.x, xv.z, acc[18]);
            acc[19] = fmaf(w1.x, xv.w, acc[19]);
            acc[20] = fmaf(w1.y, xv.x, acc[20]);
            acc[21] = fmaf(w1.y, xv.y, acc[21]);
            acc[22] = fmaf(w1.y, xv.z, acc[22]);
            acc[23] = fmaf(w1.y, xv.w, acc[23]);
            acc[24] = fmaf(w1.z, xv.x, acc[24]);
            acc[25] = fmaf(w1.z, xv.y, acc[25]);
            acc[26] = fmaf(w1.z, xv.z, acc[26]);
            acc[27] = fmaf(w1.z, xv.w, acc[27]);
            acc[28] = fmaf(w1.w, xv.x, acc[28]);
            acc[29] = fmaf(w1.w, xv.y, acc[29]);
            acc[30] = fmaf(w1.w, xv.z, acc[30]);
            acc[31] = fmaf(w1.w, xv.w, acc[31]);
        }
        if (warp == spw) {
#pragma unroll
            for (int k = 0; k < 8; k++) {
                float wv = wsp_s[(cbase + k) & 255];
                float4 xv = *(const float4*)&xs[buf][k][ncol];
                sp4[0] = fmaf(wv, xv.x, sp4[0]);
                sp4[1] = fmaf(wv, xv.y, sp4[1]);
                sp4[2] = fmaf(wv, xv.z, sp4[2]);
                sp4[3] = fmaf(wv, xv.w, sp4[3]);
            }
        }
        if (warp == plw) {
#pragma unroll
            for (int k = 0; k < 8; k++) {
                float4 xv = *(const float4*)&xs[buf][k][ncol];
                float t = (xv.x + xv.y) + (xv.z + xv.w);
                t += __shfl_xor_sync(0xffffffffu, t, 16);
                t += __shfl_xor_sync(0xffffffffu, t, 8);
                t += __shfl_xor_sync(0xffffffffu, t, 4);
                t += __shfl_xor_sync(0xffffffffu, t, 2);
                t += __shfl_xor_sync(0xffffffffu, t, 1);
                if (lane == 0) spool[cbase + k] = t;
            }
        }
        if (more) {
#pragma unroll
            for (int k = 0; k < 8; k++) xs[buf ^ 1][k][tid] = pf[k];
        }
        __syncthreads();
        buf ^= 1;
    }

    // store feat (8 coalesced STG.128 per thread)
#pragma unroll
    for (int rl = 0; rl < 8; rl++) {
        float4 v = make_float4(acc[rl * 4 + 0], acc[rl * 4 + 1],
                               acc[rl * 4 + 2], acc[rl * 4 + 3]);
        *(float4*)&g_feat[((size_t)(b * R + r0 + rl)) * HW + n0 + ncol] = v;
    }
    if (warp == spw)
        *(float4*)&g_sp[(size_t)b * HW + n0 + ncol] =
            make_float4(sp4[0], sp4[1], sp4[2], sp4[3]);
    // spool fully written (last-iteration sync); coalesced pooled-partial store
    for (int idx = tid; idx < C; idx += T1)
        g_poolpart[((size_t)(b * NSLOT) + tile) * C + idx] = spool[idx];
}

// ============================================================================
// Pass 2a: raw Gram partials. CTA = (b, n-quarter of 256), 256 threads.
// G_q[r][s] = sum_{n in q} feat[r,n]*feat[s,n]  (no centering needed here)
// ============================================================================
__global__ __launch_bounds__(256) void pass2a() {
    __shared__ __align__(16) float fcT[256][36];
    int b = blockIdx.x >> 2;
    int q = blockIdx.x & 3;
    int tid = threadIdx.x;

    for (int idx = tid; idx < R * 256; idx += 256) {
        int r = idx >> 8, n = idx & 255;
        fcT[n][r] = g_feat[((size_t)(b * R + r)) * HW + q * 256 + n];
    }
    __syncthreads();

    int my_r = tid >> 3;
    int s0 = (tid & 7) << 2;
    float g4[4] = {0.f, 0.f, 0.f, 0.f};
#pragma unroll 8
    for (int n = 0; n < 256; n++) {
        float fr = fcT[n][my_r];
        float4 fs = *(const float4*)&fcT[n][s0];
        g4[0] = fmaf(fr, fs.x, g4[0]);
        g4[1] = fmaf(fr, fs.y, g4[1]);
        g4[2] = fmaf(fr, fs.z, g4[2]);
        g4[3] = fmaf(fr, fs.w, g4[3]);
    }
    *(float4*)&g_covpart[((size_t)(b * 4 + q)) * (R * R) + my_r * R + s0] =
        make_float4(g4[0], g4[1], g4[2], g4[3]);
}

// ============================================================================
// Pass 2b: per-batch finish. pooled -> MLP (g_ca) + mu; cov assembly from
// Gram partials; power iteration; att projection + min/max + sigmoids.
// ============================================================================
__global__ __launch_bounds__(256) void pass2b(const float* __restrict__ w_fc1,
                                              const float* __restrict__ b_fc1,
                                              const float* __restrict__ w_fc2,
                                              const float* __restrict__ b_fc2,
                                              const float* __restrict__ w_eig,
                                              const float* __restrict__ b_sp,
                                              const float* __restrict__ v0) {
    __shared__ float s_pool[C];
    __shared__ float s_mu[R];
    __shared__ float s_ca1[R];
    __shared__ float s_cov[R * R];
    __shared__ float s_v[R];
    __shared__ float s_redmin[8], s_redmax[8];
    __shared__ float s_c0, s_amin, s_amax;

    int b = blockIdx.x;
    int tid = threadIdx.x, lane = tid & 31, warp = tid >> 5;

    // 1. pooled = sum of 8 tile partials / HW
    for (int c = tid; c < C; c += 256) {
        float s = 0.f;
#pragma unroll
        for (int k = 0; k < NSLOT; k++) s += g_poolpart[((size_t)b * NSLOT + k) * C + c];
        s_pool[c] = s * (1.0f / HW);
    }
    __syncthreads();

    // 2. ca1 = relu(pooled @ w_fc1^T + b_fc1); mu = w_eig @ pooled
    for (int k = 0; k < 4; k++) {
        int r = warp + k * 8;
        float s1 = 0.f, s2 = 0.f;
        for (int c = lane; c < C; c += 32) {
            float p = s_pool[c];
            s1 = fmaf(p, w_fc1[r * C + c], s1);
            s2 = fmaf(p, w_eig[r * C + c], s2);
        }
        for (int o = 16; o > 0; o >>= 1) {
            s1 += __shfl_xor_sync(0xffffffffu, s1, o);
            s2 += __shfl_xor_sync(0xffffffffu, s2, o);
        }
        if (lane == 0) {
            s_ca1[r] = fmaxf(s1 + b_fc1[r], 0.f);
            s_mu[r] = s2;
        }
    }
    __syncthreads();

    // 3. channel attention: sigmoid(ca1 @ w_fc2^T + b_fc2)
    for (int c = tid; c < C; c += 256) {
        float a = b_fc2[c];
#pragma unroll
        for (int r = 0; r < R; r++) a = fmaf(s_ca1[r], w_fc2[c * R + r], a);
        g_ca[(size_t)b * C + c] = 1.f / (1.f + expf(-a));
    }

    // 4. cov = (sum_q G_q - HW*mu*mu^T)/(HW-1) + 1e-5 I
    for (int e0 = tid * 4; e0 < R * R; e0 += 256 * 4) {
#pragma unroll
        for (int i = 0; i < 4; i++) {
            int e = e0 + i;
            int r = e >> 5, s = e & 31;
            float g = 0.f;
#pragma unroll
            for (int q = 0; q < 4; q++)
                g += g_covpart[((size_t)(b * 4 + q)) * (R * R) + e];
            float v = (g - (float)HW * s_mu[r] * s_mu[s]) * (1.0f / (HW - 1));
            if (r == s) v += 1e-5f;
            s_cov[e] = v;
        }
    }
    __syncthreads();

    // 5. power iteration (warp 0)
    if (warp == 0) {
        float v = v0[b * R + lane];
        float nr = v * v;
        for (int o = 16; o > 0; o >>= 1) nr += __shfl_xor_sync(0xffffffffu, nr, o);
        v = v / sqrtf(nr);
        for (int it = 0; it < 5; it++) {
            float nv = 0.f;
#pragma unroll
            for (int s = 0; s < R; s++)
                nv = fmaf(s_cov[s * R + lane], __shfl_sync(0xffffffffu, v, s), nv);
            float nn = nv * nv;
            for (int o = 16; o > 0; o >>= 1) nn += __shfl_xor_sync(0xffffffffu, nn, o);
            v = nv / (sqrtf(nn) + 1e-10f);
        }
        s_v[lane] = v;
        float c0 = v * s_mu[lane];
        for (int o = 16; o > 0; o >>= 1) c0 += __shfl_xor_sync(0xffffffffu, c0, o);
        if (lane == 0) s_c0 = c0;
    }
    __syncthreads();

    // 6. att[n] = v . feat_raw[:,n] - c0 ; min/max; sigmoids
    float attv[4];
#pragma unroll
    for (int k = 0; k < 4; k++) {
        int n = k * 256 + tid;
        float a = 0.f;
#pragma unroll
        for (int r = 0; r < R; r++)
            a = fmaf(s_v[r], g_feat[((size_t)(b * R + r)) * HW + n], a);
        attv[k] = a - s_c0;
    }
    float mn = attv[0], mx = attv[0];
#pragma unroll
    for (int k = 1; k < 4; k++) { mn = fminf(mn, attv[k]); mx = fmaxf(mx, attv[k]); }
    for (int o = 16; o > 0; o >>= 1) {
        mn = fminf(mn, __shfl_xor_sync(0xffffffffu, mn, o));
        mx = fmaxf(mx, __shfl_xor_sync(0xffffffffu, mx, o));
    }
    if (lane == 0) { s_redmin[warp] = mn; s_redmax[warp] = mx; }
    __syncthreads();
    if (tid == 0) {
        float a = s_redmin[0], m = s_redmax[0];
        for (int w = 1; w < 8; w++) { a = fminf(a, s_redmin[w]); m = fmaxf(m, s_redmax[w]); }
        s_amin = a; s_amax = m;
    }
    __syncthreads();
    float amin = s_amin;
    float denom = (s_amax - amin) + 1e-10f;
    float bspv = b_sp[0];
#pragma unroll
    for (int k = 0; k < 4; k++) {
        int n = k * 256 + tid;
        float e = 1.f / (1.f + expf(-((attv[k] - amin) / denom)));
        float sl = g_sp[(size_t)b * HW + n] + bspv;
        float sa = 1.f / (1.f + expf(-sl));
        g_att[(size_t)b * HW + n] = e * sa;
    }
}

// ============================================================================
// Pass 3: out = x * (1 + ca[b,c] * att[b,n])  (float4 vectorized)
// ============================================================================
__global__ __launch_bounds__(256) void pass3(const float* __restrict__ x,
                                             float* __restrict__ out) {
    unsigned int i = blockIdx.x * 256u + threadIdx.x;  // float4 index
    int n4 = i & 255;             // HW/4 = 256
    int c = (i >> 8) & (C - 1);
    int b = i >> 17;
    float ca = g_ca[b * C + c];
    float4 at = ((const float4*)g_att)[(size_t)b * (HW / 4) + n4];
    float4 xv = ((const float4*)x)[i];
    float4 o;
    o.x = fmaf(xv.x, ca * at.x, xv.x);
    o.y = fmaf(xv.y, ca * at.y, xv.y);
    o.z = fmaf(xv.z, ca * at.z, xv.z);
    o.w = fmaf(xv.w, ca * at.w, xv.w);
    ((float4*)out)[i] = o;
}

extern "C" void kernel_launch(void* const* d_in, const int* in_sizes, int n_in,
                              void* d_out, int out_size) {
    const float* x     = (const float*)d_in[0];
    const float* w_fc1 = (const float*)d_in[1];
    const float* b_fc1 = (const float*)d_in[2];
    const float* w_fc2 = (const float*)d_in[3];
    const float* b_fc2 = (const float*)d_in[4];
    const float* w_eig = (const float*)d_in[5];
    /* d_in[6] = b_eig: cancels in feat_c and in mu -> unused */
    const float* w_sp  = (const float*)d_in[7];
    const float* b_sp  = (const float*)d_in[8];
    const float* v0    = (const float*)d_in[9];
    float* out = (float*)d_out;

    pass1<<<B * NTILE, T1>>>(x, w_eig, w_sp);
    pass2a<<<B * 4, 256>>>();
    pass2b<<<B, 256>>>(w_fc1, b_fc1, w_fc2, b_fc2, w_eig, b_sp, v0);
    pass3<<<(B * C * HW / 4) / 256, 256>>>(x, out);
}

// round 4
// speedup vs baseline: 1.9107x; 1.0226x over previous
#include <cuda_runtime.h>
#include <math.h>

#define B 64
#define C 512
#define HW 1024
#define R 32
#define T1 128
#define NTILE 8        // HW / 128
#define NSLOT 8        // one pooled partial per tile

typedef unsigned long long ull;

// packed f32x2 helpers (Blackwell sm_100a+)
#define PACKDUP(d, v) \
    asm("mov.b64 %0, {%1, %1};" : "=l"(d) : "r"(__float_as_uint(v)))
#define FMA2(d, a, b) \
    asm("fma.rn.f32x2 %0, %1, %2, %0;" : "+l"(d) : "l"(a), "l"(b))
#define UNPK2(lo, hi, p) \
    asm("mov.b64 {%0, %1}, %2;" : "=r"(lo), "=r"(hi) : "l"(p))

// ---------------- scratch (device globals: no allocation allowed) -------------
__device__ float g_feat[B * R * HW];        // 8 MB   feat_raw = w_eig @ x (no bias)
__device__ float g_poolpart[B * NSLOT * C]; // 1 MB   partial sums for pooled
__device__ float g_covpart[B * 4 * R * R];  // 1 MB   raw Gram partials
__device__ float g_sp[B * HW];              // 256 KB spatial logits (no bias)
__device__ float g_ca[B * C];               // 128 KB channel attention
__device__ float g_att[B * HW];             // 256 KB eigen_att * spatial_att

// ============================================================================
// Pass 1: register-tiled GEMM with packed FFMA2. CTA = (b, 128-n tile),
// 128 threads, thread tile 8r x 4n held as 16 f32x2 accumulators (r-pairs).
// Weights loaded as natural ulonglong2 pairs (broadcast LDS), x packed (x,x).
// Per channel per thread: 16 FFMA2 + 4 mov + 3 LDS  ->  fma-pipe bound at
// 2 FMAs/FFMA2. x double-buffered via smem in chunks of 8 channels.
// ============================================================================
__global__ __launch_bounds__(T1, 4) void pass1(const float* __restrict__ x,
                                               const float* __restrict__ w_eig,
                                               const float* __restrict__ w_sp) {
    __shared__ __align__(16) float we_s[256][36];   // 36 KB, rows 144B (16B-aligned)
    __shared__ __align__(16) float xs[2][8][128];   // 8 KB double buffer
    __shared__ float wsp_s[256];
    __shared__ float spool[512];

    int b = blockIdx.x >> 3;
    int tile = blockIdx.x & 7;
    int n0 = tile << 7;
    int tid = threadIdx.x, lane = tid & 31, warp = tid >> 5;
    int r0 = warp << 3;          // 8 r rows per warp
    int ncol = lane << 2;        // 4 n cols per thread
    int spw = tile & 3;          // spatial-logit duty warp
    int plw = (tile + 1) & 3;    // pooled duty warp

    // stage w_eig half 0 (channels 0..255), transposed to [cc][r]
    for (int idx = tid; idx < 256 * 32; idx += T1) {
        int rr = idx >> 8;
        int cc = idx & 255;
        we_s[cc][rr] = w_eig[rr * C + cc];
    }
    for (int idx = tid; idx < 256; idx += T1) wsp_s[idx] = w_sp[idx];

    const float* xb = x + ((size_t)b * C) * HW + n0;

    // prefetch chunk 0
    float pf[8];
#pragma unroll
    for (int k = 0; k < 8; k++) pf[k] = xb[(size_t)k * HW + tid];
#pragma unroll
    for (int k = 0; k < 8; k++) xs[0][k][tid] = pf[k];

    ull acc[16];   // [rpair 0..3][n 0..3], each = (r=2p, r=2p+1) packed
#pragma unroll
    for (int i = 0; i < 16; i++) acc[i] = 0ull;
    float sp4[4] = {0.f, 0.f, 0.f, 0.f};

    __syncthreads();

    int buf = 0;
    for (int chunk = 0; chunk < 64; chunk++) {
        if (chunk == 32) {
            // end-of-chunk-31 sync guarantees half-0 reads of we_s are done
            for (int idx = tid; idx < 256 * 32; idx += T1) {
                int rr = idx >> 8;
                int cc = idx & 255;
                we_s[cc][rr] = w_eig[rr * C + 256 + cc];
            }
            for (int idx = tid; idx < 256; idx += T1) wsp_s[idx] = w_sp[256 + idx];
            __syncthreads();
        }
        int cbase = chunk << 3;
        bool more = chunk < 63;
        if (more) {
#pragma unroll
            for (int k = 0; k < 8; k++)
                pf[k] = xb[(size_t)(cbase + 8 + k) * HW + tid];
        }
#pragma unroll
        for (int k = 0; k < 8; k++) {
            int cl = (cbase + k) & 255;
            float4 xv = *(const float4*)&xs[buf][k][ncol];
            ull xp0, xp1, xp2, xp3;
            PACKDUP(xp0, xv.x);
            PACKDUP(xp1, xv.y);
            PACKDUP(xp2, xv.z);
            PACKDUP(xp3, xv.w);
            const ulonglong2* wrow = (const ulonglong2*)&we_s[cl][r0];
            ulonglong2 wa = wrow[0];   // (r0,r1) (r2,r3)
            ulonglong2 wb = wrow[1];   // (r4,r5) (r6,r7)
            FMA2(acc[0],  wa.x, xp0);
            FMA2(acc[1],  wa.x, xp1);
            FMA2(acc[2],  wa.x, xp2);
            FMA2(acc[3],  wa.x, xp3);
            FMA2(acc[4],  wa.y, xp0);
            FMA2(acc[5],  wa.y, xp1);
            FMA2(acc[6],  wa.y, xp2);
            FMA2(acc[7],  wa.y, xp3);
            FMA2(acc[8],  wb.x, xp0);
            FMA2(acc[9],  wb.x, xp1);
            FMA2(acc[10], wb.x, xp2);
            FMA2(acc[11], wb.x, xp3);
            FMA2(acc[12], wb.y, xp0);
            FMA2(acc[13], wb.y, xp1);
            FMA2(acc[14], wb.y, xp2);
            FMA2(acc[15], wb.y, xp3);
        }
        if (warp == spw) {
#pragma unroll
            for (int k = 0; k < 8; k++) {
                float wv = wsp_s[(cbase + k) & 255];
                float4 xv = *(const float4*)&xs[buf][k][ncol];
                sp4[0] = fmaf(wv, xv.x, sp4[0]);
                sp4[1] = fmaf(wv, xv.y, sp4[1]);
                sp4[2] = fmaf(wv, xv.z, sp4[2]);
                sp4[3] = fmaf(wv, xv.w, sp4[3]);
            }
        }
        if (warp == plw) {
#pragma unroll
            for (int k = 0; k < 8; k++) {
                float4 xv = *(const float4*)&xs[buf][k][ncol];
                float t = (xv.x + xv.y) + (xv.z + xv.w);
                t += __shfl_xor_sync(0xffffffffu, t, 16);
                t += __shfl_xor_sync(0xffffffffu, t, 8);
                t += __shfl_xor_sync(0xffffffffu, t, 4);
                t += __shfl_xor_sync(0xffffffffu, t, 2);
                t += __shfl_xor_sync(0xffffffffu, t, 1);
                if (lane == 0) spool[cbase + k] = t;
            }
        }
        if (more) {
#pragma unroll
            for (int k = 0; k < 8; k++) xs[buf ^ 1][k][tid] = pf[k];
        }
        __syncthreads();
        buf ^= 1;
    }

    // unpack r-pairs -> accf[r_local][n]
    float accf[8][4];
#pragma unroll
    for (int rp = 0; rp < 4; rp++) {
#pragma unroll
        for (int n = 0; n < 4; n++) {
            unsigned int lo, hi;
            UNPK2(lo, hi, acc[rp * 4 + n]);
            accf[2 * rp + 0][n] = __uint_as_float(lo);
            accf[2 * rp + 1][n] = __uint_as_float(hi);
        }
    }
#pragma unroll
    for (int rl = 0; rl < 8; rl++) {
        float4 v = make_float4(accf[rl][0], accf[rl][1], accf[rl][2], accf[rl][3]);
        *(float4*)&g_feat[((size_t)(b * R + r0 + rl)) * HW + n0 + ncol] = v;
    }
    if (warp == spw)
        *(float4*)&g_sp[(size_t)b * HW + n0 + ncol] =
            make_float4(sp4[0], sp4[1], sp4[2], sp4[3]);
    for (int idx = tid; idx < C; idx += T1)
        g_poolpart[((size_t)(b * NSLOT) + tile) * C + idx] = spool[idx];
}

// ============================================================================
// Pass 2a: raw Gram partials. CTA = (b, n-quarter of 256), 256 threads.
// ============================================================================
__global__ __launch_bounds__(256) void pass2a() {
    __shared__ __align__(16) float fcT[256][36];
    int b = blockIdx.x >> 2;
    int q = blockIdx.x & 3;
    int tid = threadIdx.x;

    for (int idx = tid; idx < R * 256; idx += 256) {
        int r = idx >> 8, n = idx & 255;
        fcT[n][r] = g_feat[((size_t)(b * R + r)) * HW + q * 256 + n];
    }
    __syncthreads();

    int my_r = tid >> 3;
    int s0 = (tid & 7) << 2;
    float g4[4] = {0.f, 0.f, 0.f, 0.f};
#pragma unroll 8
    for (int n = 0; n < 256; n++) {
        float fr = fcT[n][my_r];
        float4 fs = *(const float4*)&fcT[n][s0];
        g4[0] = fmaf(fr, fs.x, g4[0]);
        g4[1] = fmaf(fr, fs.y, g4[1]);
        g4[2] = fmaf(fr, fs.z, g4[2]);
        g4[3] = fmaf(fr, fs.w, g4[3]);
    }
    *(float4*)&g_covpart[((size_t)(b * 4 + q)) * (R * R) + my_r * R + s0] =
        make_float4(g4[0], g4[1], g4[2], g4[3]);
}

// ============================================================================
// Pass 2b: per-batch finish. pooled -> MLP (g_ca) + mu; cov assembly;
// power iteration; att projection + min/max + sigmoids.
// ============================================================================
__global__ __launch_bounds__(256) void pass2b(const float* __restrict__ w_fc1,
                                              const float* __restrict__ b_fc1,
                                              const float* __restrict__ w_fc2,
                                              const float* __restrict__ b_fc2,
                                              const float* __restrict__ w_eig,
                                              const float* __restrict__ b_sp,
                                              const float* __restrict__ v0) {
    __shared__ float s_pool[C];
    __shared__ float s_mu[R];
    __shared__ float s_ca1[R];
    __shared__ float s_cov[R * R];
    __shared__ float s_v[R];
    __shared__ float s_redmin[8], s_redmax[8];
    __shared__ float s_c0, s_amin, s_amax;

    int b = blockIdx.x;
    int tid = threadIdx.x, lane = tid & 31, warp = tid >> 5;

    // 1. pooled = sum of 8 tile partials / HW
    for (int c = tid; c < C; c += 256) {
        float s = 0.f;
#pragma unroll
        for (int k = 0; k < NSLOT; k++) s += g_poolpart[((size_t)b * NSLOT + k) * C + c];
        s_pool[c] = s * (1.0f / HW);
    }
    __syncthreads();

    // 2. ca1 = relu(pooled @ w_fc1^T + b_fc1); mu = w_eig @ pooled
    for (int k = 0; k < 4; k++) {
        int r = warp + k * 8;
        float s1 = 0.f, s2 = 0.f;
        for (int c = lane; c < C; c += 32) {
            float p = s_pool[c];
            s1 = fmaf(p, w_fc1[r * C + c], s1);
            s2 = fmaf(p, w_eig[r * C + c], s2);
        }
        for (int o = 16; o > 0; o >>= 1) {
            s1 += __shfl_xor_sync(0xffffffffu, s1, o);
            s2 += __shfl_xor_sync(0xffffffffu, s2, o);
        }
        if (lane == 0) {
            s_ca1[r] = fmaxf(s1 + b_fc1[r], 0.f);
            s_mu[r] = s2;
        }
    }
    __syncthreads();

    // 3. channel attention: sigmoid(ca1 @ w_fc2^T + b_fc2)
    for (int c = tid; c < C; c += 256) {
        float a = b_fc2[c];
#pragma unroll
        for (int r = 0; r < R; r++) a = fmaf(s_ca1[r], w_fc2[c * R + r], a);
        g_ca[(size_t)b * C + c] = 1.f / (1.f + expf(-a));
    }

    // 4. cov = (sum_q G_q - HW*mu*mu^T)/(HW-1) + 1e-5 I
    for (int e0 = tid * 4; e0 < R * R; e0 += 256 * 4) {
#pragma unroll
        for (int i = 0; i < 4; i++) {
            int e = e0 + i;
            int r = e >> 5, s = e & 31;
            float g = 0.f;
#pragma unroll
            for (int q = 0; q < 4; q++)
                g += g_covpart[((size_t)(b * 4 + q)) * (R * R) + e];
            float v = (g - (float)HW * s_mu[r] * s_mu[s]) * (1.0f / (HW - 1));
            if (r == s) v += 1e-5f;
            s_cov[e] = v;
        }
    }
    __syncthreads();

    // 5. power iteration (warp 0)
    if (warp == 0) {
        float v = v0[b * R + lane];
        float nr = v * v;
        for (int o = 16; o > 0; o >>= 1) nr += __shfl_xor_sync(0xffffffffu, nr, o);
        v = v / sqrtf(nr);
        for (int it = 0; it < 5; it++) {
            float nv = 0.f;
#pragma unroll
            for (int s = 0; s < R; s++)
                nv = fmaf(s_cov[s * R + lane], __shfl_sync(0xffffffffu, v, s), nv);
            float nn = nv * nv;
            for (int o = 16; o > 0; o >>= 1) nn += __shfl_xor_sync(0xffffffffu, nn, o);
            v = nv / (sqrtf(nn) + 1e-10f);
        }
        s_v[lane] = v;
        float c0 = v * s_mu[lane];
        for (int o = 16; o > 0; o >>= 1) c0 += __shfl_xor_sync(0xffffffffu, c0, o);
        if (lane == 0) s_c0 = c0;
    }
    __syncthreads();

    // 6. att[n] = v . feat_raw[:,n] - c0 ; min/max; sigmoids
    float attv[4];
#pragma unroll
    for (int k = 0; k < 4; k++) {
        int n = k * 256 + tid;
        float a = 0.f;
#pragma unroll
        for (int r = 0; r < R; r++)
            a = fmaf(s_v[r], g_feat[((size_t)(b * R + r)) * HW + n], a);
        attv[k] = a - s_c0;
    }
    float mn = attv[0], mx = attv[0];
#pragma unroll
    for (int k = 1; k < 4; k++) { mn = fminf(mn, attv[k]); mx = fmaxf(mx, attv[k]); }
    for (int o = 16; o > 0; o >>= 1) {
        mn = fminf(mn, __shfl_xor_sync(0xffffffffu, mn, o));
        mx = fmaxf(mx, __shfl_xor_sync(0xffffffffu, mx, o));
    }
    if (lane == 0) { s_redmin[warp] = mn; s_redmax[warp] = mx; }
    __syncthreads();
    if (tid == 0) {
        float a = s_redmin[0], m = s_redmax[0];
        for (int w = 1; w < 8; w++) { a = fminf(a, s_redmin[w]); m = fmaxf(m, s_redmax[w]); }
        s_amin = a; s_amax = m;
    }
    __syncthreads();
    float amin = s_amin;
    float denom = (s_amax - amin) + 1e-10f;
    float bspv = b_sp[0];
#pragma unroll
    for (int k = 0; k < 4; k++) {
        int n = k * 256 + tid;
        float e = 1.f / (1.f + expf(-((attv[k] - amin) / denom)));
        float sl = g_sp[(size_t)b * HW + n] + bspv;
        float sa = 1.f / (1.f + expf(-sl));
        g_att[(size_t)b * HW + n] = e * sa;
    }
}

// ============================================================================
// Pass 3: out = x * (1 + ca[b,c] * att[b,n])  (2x float4 per thread)
// ============================================================================
__global__ __launch_bounds__(256) void pass3(const float* __restrict__ x,
                                             float* __restrict__ out) {
    unsigned int base = blockIdx.x * 512u + threadIdx.x;
#pragma unroll
    for (int u = 0; u < 2; u++) {
        unsigned int i = base + u * 256u;      // float4 index
        int n4 = i & 255;                      // HW/4 = 256
        int c = (i >> 8) & (C - 1);
        int b = i >> 17;
        float ca = g_ca[b * C + c];
        float4 at = ((const float4*)g_att)[(size_t)b * (HW / 4) + n4];
        float4 xv = ((const float4*)x)[i];
        float4 o;
        o.x = fmaf(xv.x, ca * at.x, xv.x);
        o.y = fmaf(xv.y, ca * at.y, xv.y);
        o.z = fmaf(xv.z, ca * at.z, xv.z);
        o.w = fmaf(xv.w, ca * at.w, xv.w);
        ((float4*)out)[i] = o;
    }
}

extern "C" void kernel_launch(void* const* d_in, const int* in_sizes, int n_in,
                              void* d_out, int out_size) {
    const float* x     = (const float*)d_in[0];
    const float* w_fc1 = (const float*)d_in[1];
    const float* b_fc1 = (const float*)d_in[2];
    const float* w_fc2 = (const float*)d_in[3];
    const float* b_fc2 = (const float*)d_in[4];
    const float* w_eig = (const float*)d_in[5];
    /* d_in[6] = b_eig: cancels in feat_c and in mu -> unused */
    const float* w_sp  = (const float*)d_in[7];
    const float* b_sp  = (const float*)d_in[8];
    const float* v0    = (const float*)d_in[9];
    float* out = (float*)d_out;

    pass1<<<B * NTILE, T1>>>(x, w_eig, w_sp);
    pass2a<<<B * 4, 256>>>();
    pass2b<<<B, 256>>>(w_fc1, b_fc1, w_fc2, b_fc2, w_eig, b_sp, v0);
    pass3<<<(B * C * HW / 4) / 512, 256>>>(x, out);
}